// round 7
// baseline (speedup 1.0000x reference)
#include <cuda_runtime.h>

// DWHT (buggy torch in-place semantics) + channel shuffle, fully fused.
// x: (64, 256, 28, 28) f32  ->  out: (64, 512, 28, 28) f32
//
// 8 passes = (F o F)^4. G = F o F maps each aligned 16-channel chunk to a
// fixed signed output set. Channel shuffle (groups=8): ch->((ch&63)<<3)|(ch>>6).
//
// Round-6 geometry: NPIX=16 pixels/block, 256 threads, PAIR-PACKED fp32 smem:
//   sidx(c,p) = (c/2)*32 + 2p + (c&1)
// so chunk reads are 8x LDS.64 and most stores are STS.64, all at the
// bandwidth floor (2 half-warp phases per 256B, zero bank conflicts).
// 32KB static smem -> 6 blocks/SM. Zero-pad sparsity skips dead chunk reads
// (stages 2,3) and dead zero-chunk stores (stage 2).

#define NPIX 16
#define SROW 32   // floats per channel-pair row = 2*NPIX

struct GOut {
    float4 Al;              // -> 4*jl + q
    float2 Bl, Dl, Gl;      // -> 128+2jl, 256+2jl, 384+2jl
    float  El;              // -> 320+jl
    float4 Ah, Ch, G4h;     // -> 4*jh+q, 128+4jh+q, 384+4jh+q
    float2 Bh, Dh, G2h, Fh; // -> 128+2jh, 256+2jh, 384+2jh, 320+2jh
    float  Eh;              // -> 320+jh
};

__device__ __forceinline__ GOut compute_G(const float wl[16], const float wh[16]) {
    GOut o;
    o.Al.x = wl[0]+wl[1]+wl[2]+wl[3];
    o.Al.y = wl[4]+wl[5]+wl[6]+wl[7];
    o.Al.z = wl[8]+wl[9]+wl[10]+wl[11];
    o.Al.w = wl[12]+wl[13]+wl[14]+wl[15];
    o.Bl.x = wl[0]+wl[1]-wl[2]-wl[3]+wl[4]+wl[5]-wl[6]-wl[7];
    o.Bl.y = wl[8]+wl[9]-wl[10]-wl[11]+wl[12]+wl[13]-wl[14]-wl[15];
    o.Dl.x = wl[0]+wl[1]+wl[2]+wl[3]-wl[4]-wl[5]-wl[6]-wl[7];
    o.Dl.y = wl[8]+wl[9]+wl[10]+wl[11]-wl[12]-wl[13]-wl[14]-wl[15];
    o.Gl.x = wl[0]+wl[1]-wl[2]-wl[3]-wl[4]-wl[5]+wl[6]+wl[7];
    o.Gl.y = wl[8]+wl[9]-wl[10]-wl[11]-wl[12]-wl[13]+wl[14]+wl[15];
    o.El   = wl[0]+wl[1]-wl[2]-wl[3]+wl[4]+wl[5]-wl[6]-wl[7]
            -wl[8]-wl[9]+wl[10]+wl[11]-wl[12]-wl[13]+wl[14]+wl[15];
    o.Ah.x = wh[0]+wh[1]+wh[2]+wh[3];
    o.Ah.y = wh[4]+wh[5]+wh[6]+wh[7];
    o.Ah.z = wh[8]+wh[9]+wh[10]+wh[11];
    o.Ah.w = wh[12]+wh[13]+wh[14]+wh[15];
    o.Ch.x = wh[0]-wh[1]+wh[2]-wh[3];
    o.Ch.y = wh[4]-wh[5]+wh[6]-wh[7];
    o.Ch.z = wh[8]-wh[9]+wh[10]-wh[11];
    o.Ch.w = wh[12]-wh[13]+wh[14]-wh[15];
    o.G4h.x = wh[0]-wh[1]-wh[2]+wh[3];
    o.G4h.y = wh[4]-wh[5]-wh[6]+wh[7];
    o.G4h.z = wh[8]-wh[9]-wh[10]+wh[11];
    o.G4h.w = wh[12]-wh[13]-wh[14]+wh[15];
    o.Bh.x = wh[0]+wh[1]-wh[2]-wh[3]+wh[4]+wh[5]-wh[6]-wh[7];
    o.Bh.y = wh[8]+wh[9]-wh[10]-wh[11]+wh[12]+wh[13]-wh[14]-wh[15];
    o.Dh.x = wh[0]+wh[1]+wh[2]+wh[3]-wh[4]-wh[5]-wh[6]-wh[7];
    o.Dh.y = wh[8]+wh[9]+wh[10]+wh[11]-wh[12]-wh[13]-wh[14]-wh[15];
    o.G2h.x = wh[0]+wh[1]-wh[2]-wh[3]-wh[4]-wh[5]+wh[6]+wh[7];
    o.G2h.y = wh[8]+wh[9]-wh[10]-wh[11]-wh[12]-wh[13]+wh[14]+wh[15];
    o.Fh.x = wh[0]-wh[1]+wh[2]-wh[3]-wh[4]+wh[5]-wh[6]+wh[7];
    o.Fh.y = wh[8]-wh[9]+wh[10]-wh[11]-wh[12]+wh[13]-wh[14]+wh[15];
    o.Eh   = wh[0]+wh[1]-wh[2]-wh[3]+wh[4]+wh[5]-wh[6]-wh[7]
            -wh[8]-wh[9]+wh[10]+wh[11]-wh[12]-wh[13]+wh[14]+wh[15];
    return o;
}

__device__ __forceinline__ void zero16(float w[16]) {
#pragma unroll
    for (int m = 0; m < 16; m++) w[m] = 0.0f;
}

// Read one 16-channel chunk as 8 x LDS.64 (pair-packed layout).
__device__ __forceinline__ void load_chunk(const float* __restrict__ s, int chunk,
                                           int p, float w[16]) {
#pragma unroll
    for (int i = 0; i < 8; i++) {
        float2 v = *(const float2*)(s + (8 * chunk + i) * SROW + 2 * p);
        w[2*i] = v.x; w[2*i+1] = v.y;
    }
}

__device__ __forceinline__ void sts2(float* __restrict__ s, int c, int p,
                                     float a, float b) {          // c even
    *(float2*)(s + (c >> 1) * SROW + 2 * p) = make_float2(a, b);
}
__device__ __forceinline__ void sts1(float* __restrict__ s, int c, int p, float v) {
    s[(c >> 1) * SROW + 2 * p + (c & 1)] = v;
}

__device__ __forceinline__ void store_G(float* __restrict__ s, int jl, int p,
                                        const GOut& o, bool skipAl, bool skipH4) {
    const int jh = jl + 16;
    if (!skipAl) {                       // chunks 1,3 targets when jl in 4..7/12..15
        sts2(s, 4*jl,     p, o.Al.x, o.Al.y);
        sts2(s, 4*jl + 2, p, o.Al.z, o.Al.w);
    }
    sts2(s, 128 + 2*jl, p, o.Bl.x, o.Bl.y);
    sts2(s, 256 + 2*jl, p, o.Dl.x, o.Dl.y);
    sts2(s, 384 + 2*jl, p, o.Gl.x, o.Gl.y);
    sts1(s, 320 + jl, p, o.El);
    if (!skipH4) {                       // chunks 7,15,31 targets when jl>=12
        sts2(s, 4*jh,     p, o.Ah.x, o.Ah.y);
        sts2(s, 4*jh + 2, p, o.Ah.z, o.Ah.w);
        sts2(s, 128 + 4*jh,     p, o.Ch.x, o.Ch.y);
        sts2(s, 128 + 4*jh + 2, p, o.Ch.z, o.Ch.w);
        sts2(s, 384 + 4*jh,     p, o.G4h.x, o.G4h.y);
        sts2(s, 384 + 4*jh + 2, p, o.G4h.z, o.G4h.w);
    }
    sts2(s, 128 + 2*jh, p, o.Bh.x, o.Bh.y);
    sts2(s, 256 + 2*jh, p, o.Dh.x, o.Dh.y);
    sts2(s, 384 + 2*jh, p, o.G2h.x, o.G2h.y);
    sts2(s, 320 + 2*jh, p, o.Fh.x, o.Fh.y);
    sts1(s, 320 + jh, p, o.Eh);
}

__device__ __forceinline__ void gstore(float* __restrict__ op, int idx, float v) {
    const int c = ((idx & 63) << 3) | (idx >> 6);    // groups=8 shuffle
    op[c * 784] = v;
}

__global__ __launch_bounds__(256, 6)
void dwht_kernel(const float* __restrict__ x, float* __restrict__ out) {
    __shared__ float s[256 * SROW];     // 512 channels pair-packed = 32 KB

    const int tid = threadIdx.x;
    const int p   = tid & (NPIX - 1);   // pixel within tile [0,16)
    const int jl  = tid >> 4;           // chunk pair id     [0,16)
    const int jh  = jl + 16;

    const int b  = blockIdx.x / 49;
    const int hw = (blockIdx.x % 49) * NPIX + p;    // 784 = 49*16, exact
    const float* xp = x   + (size_t)b * (256 * 784) + hw;
    float*       op = out + (size_t)b * (512 * 784) + hw;

    float wl[16], wh[16];

    // ---- stage 1: global load; high 256 channels are the zero pad ----
#pragma unroll
    for (int m = 0; m < 16; m++) wl[m] = xp[(16 * jl + m) * 784];
    zero16(wh);
    {
        GOut o = compute_G(wl, wh);     // high outputs fold to 0 and are DCE'd
        sts2(s, 4*jl,     p, o.Al.x, o.Al.y);
        sts2(s, 4*jl + 2, p, o.Al.z, o.Al.w);
        sts2(s, 128 + 2*jl, p, o.Bl.x, o.Bl.y);
        sts2(s, 256 + 2*jl, p, o.Dl.x, o.Dl.y);
        sts2(s, 384 + 2*jl, p, o.Gl.x, o.Gl.y);
        sts1(s, 320 + jl, p, o.El);
    }
    __syncthreads();

    // ---- stage 2: nonzero input chunks {0,1,2,3,8,9,16,17,20,24,25} ----
    {
        const bool rl = (jl <= 3) | (jl == 8) | (jl == 9);
        const bool rh = (jl <= 1) | (jl == 4) | (jl == 8) | (jl == 9);
        if (rl) load_chunk(s, jl, p, wl); else zero16(wl);
        if (rh) load_chunk(s, jh, p, wh); else zero16(wh);
        GOut o = compute_G(wl, wh);
        __syncthreads();                 // all reads done before overwrite
        // outputs landing in chunks {1,3,7,15,31} are exact zeros: skip stores
        const bool skipAl = ((jl >= 4) & (jl <= 7)) | (jl >= 12);
        const bool skipH4 = (jl >= 12);
        store_G(s, jl, p, o, skipAl, skipH4);
        __syncthreads();
    }

    // ---- stage 3: chunks {1,3,7,15,31} are identically zero: skip reads ----
    {
        const bool rl = !((jl == 1) | (jl == 3) | (jl == 7) | (jl == 15));
        const bool rh = (jl != 15);
        if (rl) load_chunk(s, jl, p, wl); else zero16(wl);
        if (rh) load_chunk(s, jh, p, wh); else zero16(wh);
        GOut o = compute_G(wl, wh);
        __syncthreads();
        store_G(s, jl, p, o, false, false);
        __syncthreads();
    }

    // ---- stage 4: smem -> registers -> shuffled global store ----
    load_chunk(s, jl, p, wl);
    load_chunk(s, jh, p, wh);
    {
        GOut o = compute_G(wl, wh);
        gstore(op, 4*jl+0, o.Al.x); gstore(op, 4*jl+1, o.Al.y);
        gstore(op, 4*jl+2, o.Al.z); gstore(op, 4*jl+3, o.Al.w);
        gstore(op, 128+2*jl+0, o.Bl.x); gstore(op, 128+2*jl+1, o.Bl.y);
        gstore(op, 256+2*jl+0, o.Dl.x); gstore(op, 256+2*jl+1, o.Dl.y);
        gstore(op, 384+2*jl+0, o.Gl.x); gstore(op, 384+2*jl+1, o.Gl.y);
        gstore(op, 320+jl, o.El);
        gstore(op, 4*jh+0, o.Ah.x); gstore(op, 4*jh+1, o.Ah.y);
        gstore(op, 4*jh+2, o.Ah.z); gstore(op, 4*jh+3, o.Ah.w);
        gstore(op, 128+4*jh+0, o.Ch.x); gstore(op, 128+4*jh+1, o.Ch.y);
        gstore(op, 128+4*jh+2, o.Ch.z); gstore(op, 128+4*jh+3, o.Ch.w);
        gstore(op, 384+4*jh+0, o.G4h.x); gstore(op, 384+4*jh+1, o.G4h.y);
        gstore(op, 384+4*jh+2, o.G4h.z); gstore(op, 384+4*jh+3, o.G4h.w);
        gstore(op, 128+2*jh+0, o.Bh.x); gstore(op, 128+2*jh+1, o.Bh.y);
        gstore(op, 256+2*jh+0, o.Dh.x); gstore(op, 256+2*jh+1, o.Dh.y);
        gstore(op, 384+2*jh+0, o.G2h.x); gstore(op, 384+2*jh+1, o.G2h.y);
        gstore(op, 320+2*jh+0, o.Fh.x); gstore(op, 320+2*jh+1, o.Fh.y);
        gstore(op, 320+jh, o.Eh);
    }
}

extern "C" void kernel_launch(void* const* d_in, const int* in_sizes, int n_in,
                              void* d_out, int out_size) {
    const float* x = (const float*)d_in[0];
    float* out = (float*)d_out;
    // 64 images * 49 pixel-tiles of 16 (exact: 784 = 49*16)
    dwht_kernel<<<64 * 49, 256>>>(x, out);
}

// round 8
// speedup vs baseline: 1.1718x; 1.1718x over previous
#include <cuda_runtime.h>

// DWHT (buggy torch in-place semantics) + channel shuffle, fully fused.
// x: (64, 256, 28, 28) f32  ->  out: (64, 512, 28, 28) f32
//
// 8 passes = (F o F)^4. G = F o F maps each aligned 16-channel chunk to a
// fixed signed output set. Channel shuffle (groups=8): ch->((ch&63)<<3)|(ch>>6).
//
// Round-7 geometry = Round-5 (best) + pair-packed smem:
//   warp = 32 pixels x 1 chunk-pair, NPIX=32 (full 128B global coalescing),
//   smem sidx(c,p) = (c/2)*64 + 2p + (c&1)  -> chunk reads are 8x LDS.64,
//   most stores STS.64; half-warps each cover all 32 banks -> conflict-free,
//   wavefronts at the bandwidth floor with HALF the smem instructions.
// Zero-pad sparsity: stage-1 stores only the 11 live outputs; stage 2 reads
// only nonzero chunks and skips stores into still-zero chunks; stage 3 skips
// zero-chunk reads. 64KB dynamic smem, 3 blocks/SM.

#define NPIX 32
#define SROW 64   // floats per channel-pair row = 2*NPIX

struct GOut {
    float4 Al;              // -> 4*jl + q
    float2 Bl, Dl, Gl;      // -> 128+2jl, 256+2jl, 384+2jl
    float  El;              // -> 320+jl
    float4 Ah, Ch, G4h;     // -> 4*jh+q, 128+4jh+q, 384+4jh+q
    float2 Bh, Dh, G2h, Fh; // -> 128+2jh, 256+2jh, 384+2jh, 320+2jh
    float  Eh;              // -> 320+jh
};

__device__ __forceinline__ GOut compute_G(const float wl[16], const float wh[16]) {
    GOut o;
    o.Al.x = wl[0]+wl[1]+wl[2]+wl[3];
    o.Al.y = wl[4]+wl[5]+wl[6]+wl[7];
    o.Al.z = wl[8]+wl[9]+wl[10]+wl[11];
    o.Al.w = wl[12]+wl[13]+wl[14]+wl[15];
    o.Bl.x = wl[0]+wl[1]-wl[2]-wl[3]+wl[4]+wl[5]-wl[6]-wl[7];
    o.Bl.y = wl[8]+wl[9]-wl[10]-wl[11]+wl[12]+wl[13]-wl[14]-wl[15];
    o.Dl.x = wl[0]+wl[1]+wl[2]+wl[3]-wl[4]-wl[5]-wl[6]-wl[7];
    o.Dl.y = wl[8]+wl[9]+wl[10]+wl[11]-wl[12]-wl[13]-wl[14]-wl[15];
    o.Gl.x = wl[0]+wl[1]-wl[2]-wl[3]-wl[4]-wl[5]+wl[6]+wl[7];
    o.Gl.y = wl[8]+wl[9]-wl[10]-wl[11]-wl[12]-wl[13]+wl[14]+wl[15];
    o.El   = wl[0]+wl[1]-wl[2]-wl[3]+wl[4]+wl[5]-wl[6]-wl[7]
            -wl[8]-wl[9]+wl[10]+wl[11]-wl[12]-wl[13]+wl[14]+wl[15];
    o.Ah.x = wh[0]+wh[1]+wh[2]+wh[3];
    o.Ah.y = wh[4]+wh[5]+wh[6]+wh[7];
    o.Ah.z = wh[8]+wh[9]+wh[10]+wh[11];
    o.Ah.w = wh[12]+wh[13]+wh[14]+wh[15];
    o.Ch.x = wh[0]-wh[1]+wh[2]-wh[3];
    o.Ch.y = wh[4]-wh[5]+wh[6]-wh[7];
    o.Ch.z = wh[8]-wh[9]+wh[10]-wh[11];
    o.Ch.w = wh[12]-wh[13]+wh[14]-wh[15];
    o.G4h.x = wh[0]-wh[1]-wh[2]+wh[3];
    o.G4h.y = wh[4]-wh[5]-wh[6]+wh[7];
    o.G4h.z = wh[8]-wh[9]-wh[10]+wh[11];
    o.G4h.w = wh[12]-wh[13]-wh[14]+wh[15];
    o.Bh.x = wh[0]+wh[1]-wh[2]-wh[3]+wh[4]+wh[5]-wh[6]-wh[7];
    o.Bh.y = wh[8]+wh[9]-wh[10]-wh[11]+wh[12]+wh[13]-wh[14]-wh[15];
    o.Dh.x = wh[0]+wh[1]+wh[2]+wh[3]-wh[4]-wh[5]-wh[6]-wh[7];
    o.Dh.y = wh[8]+wh[9]+wh[10]+wh[11]-wh[12]-wh[13]-wh[14]-wh[15];
    o.G2h.x = wh[0]+wh[1]-wh[2]-wh[3]-wh[4]-wh[5]+wh[6]+wh[7];
    o.G2h.y = wh[8]+wh[9]-wh[10]-wh[11]-wh[12]-wh[13]+wh[14]+wh[15];
    o.Fh.x = wh[0]-wh[1]+wh[2]-wh[3]-wh[4]+wh[5]-wh[6]+wh[7];
    o.Fh.y = wh[8]-wh[9]+wh[10]-wh[11]-wh[12]+wh[13]-wh[14]+wh[15];
    o.Eh   = wh[0]+wh[1]-wh[2]-wh[3]+wh[4]+wh[5]-wh[6]-wh[7]
            -wh[8]-wh[9]+wh[10]+wh[11]-wh[12]-wh[13]+wh[14]+wh[15];
    return o;
}

__device__ __forceinline__ void zero16(float w[16]) {
#pragma unroll
    for (int m = 0; m < 16; m++) w[m] = 0.0f;
}

// Read one 16-channel chunk as 8 x LDS.64 (pair-packed layout).
__device__ __forceinline__ void load_chunk(const float* __restrict__ s, int chunk,
                                           int p, float w[16]) {
#pragma unroll
    for (int i = 0; i < 8; i++) {
        float2 v = *(const float2*)(s + (8 * chunk + i) * SROW + 2 * p);
        w[2*i] = v.x; w[2*i+1] = v.y;
    }
}

__device__ __forceinline__ void sts2(float* __restrict__ s, int c, int p,
                                     float a, float b) {          // c even
    *(float2*)(s + (c >> 1) * SROW + 2 * p) = make_float2(a, b);
}
__device__ __forceinline__ void sts1(float* __restrict__ s, int c, int p, float v) {
    s[(c >> 1) * SROW + 2 * p + (c & 1)] = v;
}

__device__ __forceinline__ void store_G(float* __restrict__ s, int jl, int p,
                                        const GOut& o, bool skipAl, bool skipH4) {
    const int jh = jl + 16;
    if (!skipAl) {                        // targets in dead chunks 1,3 when skipped
        sts2(s, 4*jl,     p, o.Al.x, o.Al.y);
        sts2(s, 4*jl + 2, p, o.Al.z, o.Al.w);
    }
    sts2(s, 128 + 2*jl, p, o.Bl.x, o.Bl.y);
    sts2(s, 256 + 2*jl, p, o.Dl.x, o.Dl.y);
    sts2(s, 384 + 2*jl, p, o.Gl.x, o.Gl.y);
    sts1(s, 320 + jl, p, o.El);
    if (!skipH4) {                        // targets in dead chunks 7,15,31
        sts2(s, 4*jh,     p, o.Ah.x, o.Ah.y);
        sts2(s, 4*jh + 2, p, o.Ah.z, o.Ah.w);
        sts2(s, 128 + 4*jh,     p, o.Ch.x, o.Ch.y);
        sts2(s, 128 + 4*jh + 2, p, o.Ch.z, o.Ch.w);
        sts2(s, 384 + 4*jh,     p, o.G4h.x, o.G4h.y);
        sts2(s, 384 + 4*jh + 2, p, o.G4h.z, o.G4h.w);
    }
    sts2(s, 128 + 2*jh, p, o.Bh.x, o.Bh.y);
    sts2(s, 256 + 2*jh, p, o.Dh.x, o.Dh.y);
    sts2(s, 384 + 2*jh, p, o.G2h.x, o.G2h.y);
    sts2(s, 320 + 2*jh, p, o.Fh.x, o.Fh.y);
    sts1(s, 320 + jh, p, o.Eh);
}

__device__ __forceinline__ void gstore(float* __restrict__ op, int idx, float v) {
    const int c = ((idx & 63) << 3) | (idx >> 6);    // groups=8 shuffle
    op[c * 784] = v;
}

__global__ __launch_bounds__(512, 3)
void dwht_kernel(const float* __restrict__ x, float* __restrict__ out) {
    extern __shared__ float s[];        // 256 pair-rows x 64 floats = 64 KB

    const int tid = threadIdx.x;
    const int p   = tid & (NPIX - 1);   // pixel lane within warp [0,32)
    const int jl  = tid >> 5;           // chunk pair id = warp id [0,16)
    const int jh  = jl + 16;

    const int b    = blockIdx.x / 25;
    const int hw   = (blockIdx.x % 25) * NPIX + p;
    const bool valid = (hw < 784);
    const float* xp = x   + (size_t)b * (256 * 784) + hw;
    float*       op = out + (size_t)b * (512 * 784) + hw;

    float wl[16], wh[16];

    // ---- stage 1: global load; high 256 channels are the zero pad ----
#pragma unroll
    for (int m = 0; m < 16; m++) wl[m] = valid ? xp[(16 * jl + m) * 784] : 0.0f;
    zero16(wh);
    {
        GOut o = compute_G(wl, wh);     // high outputs fold to 0 and are DCE'd
        sts2(s, 4*jl,     p, o.Al.x, o.Al.y);
        sts2(s, 4*jl + 2, p, o.Al.z, o.Al.w);
        sts2(s, 128 + 2*jl, p, o.Bl.x, o.Bl.y);
        sts2(s, 256 + 2*jl, p, o.Dl.x, o.Dl.y);
        sts2(s, 384 + 2*jl, p, o.Gl.x, o.Gl.y);
        sts1(s, 320 + jl, p, o.El);
    }
    __syncthreads();

    // ---- stage 2: nonzero input chunks {0,1,2,3,8,9,16,17,20,24,25} ----
    {
        const bool rl = (jl <= 3) | (jl == 8) | (jl == 9);
        const bool rh = (jl <= 1) | (jl == 4) | (jl == 8) | (jl == 9);
        if (rl) load_chunk(s, jl, p, wl); else zero16(wl);
        if (rh) load_chunk(s, jh, p, wh); else zero16(wh);
        GOut o = compute_G(wl, wh);
        __syncthreads();                 // all reads done before overwrite
        // outputs landing in chunks {1,3,7,15,31} are exact zeros: skip stores
        const bool skipAl = ((jl >= 4) & (jl <= 7)) | (jl >= 12);
        const bool skipH4 = (jl >= 12);
        store_G(s, jl, p, o, skipAl, skipH4);
        __syncthreads();
    }

    // ---- stage 3: chunks {1,3,7,15,31} are identically zero: skip reads ----
    {
        const bool rl = !((jl == 1) | (jl == 3) | (jl == 7) | (jl == 15));
        const bool rh = (jl != 15);
        if (rl) load_chunk(s, jl, p, wl); else zero16(wl);
        if (rh) load_chunk(s, jh, p, wh); else zero16(wh);
        GOut o = compute_G(wl, wh);
        __syncthreads();
        store_G(s, jl, p, o, false, false);
        __syncthreads();
    }

    // ---- stage 4: smem -> registers -> shuffled global store ----
    load_chunk(s, jl, p, wl);
    load_chunk(s, jh, p, wh);
    {
        GOut o = compute_G(wl, wh);
        if (valid) {
            gstore(op, 4*jl+0, o.Al.x); gstore(op, 4*jl+1, o.Al.y);
            gstore(op, 4*jl+2, o.Al.z); gstore(op, 4*jl+3, o.Al.w);
            gstore(op, 128+2*jl+0, o.Bl.x); gstore(op, 128+2*jl+1, o.Bl.y);
            gstore(op, 256+2*jl+0, o.Dl.x); gstore(op, 256+2*jl+1, o.Dl.y);
            gstore(op, 384+2*jl+0, o.Gl.x); gstore(op, 384+2*jl+1, o.Gl.y);
            gstore(op, 320+jl, o.El);
            gstore(op, 4*jh+0, o.Ah.x); gstore(op, 4*jh+1, o.Ah.y);
            gstore(op, 4*jh+2, o.Ah.z); gstore(op, 4*jh+3, o.Ah.w);
            gstore(op, 128+4*jh+0, o.Ch.x); gstore(op, 128+4*jh+1, o.Ch.y);
            gstore(op, 128+4*jh+2, o.Ch.z); gstore(op, 128+4*jh+3, o.Ch.w);
            gstore(op, 384+4*jh+0, o.G4h.x); gstore(op, 384+4*jh+1, o.G4h.y);
            gstore(op, 384+4*jh+2, o.G4h.z); gstore(op, 384+4*jh+3, o.G4h.w);
            gstore(op, 128+2*jh+0, o.Bh.x); gstore(op, 128+2*jh+1, o.Bh.y);
            gstore(op, 256+2*jh+0, o.Dh.x); gstore(op, 256+2*jh+1, o.Dh.y);
            gstore(op, 384+2*jh+0, o.G2h.x); gstore(op, 384+2*jh+1, o.G2h.y);
            gstore(op, 320+2*jh+0, o.Fh.x); gstore(op, 320+2*jh+1, o.Fh.y);
            gstore(op, 320+jh, o.Eh);
        }
    }
}

extern "C" void kernel_launch(void* const* d_in, const int* in_sizes, int n_in,
                              void* d_out, int out_size) {
    const float* x = (const float*)d_in[0];
    float* out = (float*)d_out;
    const int smem = 256 * SROW * sizeof(float);   // 64 KB
    static bool attr_set = false;                  // idempotent host-side attr
    if (!attr_set) {
        cudaFuncSetAttribute(dwht_kernel,
                             cudaFuncAttributeMaxDynamicSharedMemorySize, smem);
        attr_set = true;
    }
    // 64 images * 25 pixel-tiles of 32 (last tile predicated: 784 = 24*32+16)
    dwht_kernel<<<64 * 25, 512, smem>>>(x, out);
}